// round 1
// baseline (speedup 1.0000x reference)
#include <cuda_runtime.h>
#include <math_constants.h>

#define Bn 4
#define Qn 512
#define Kn 512
#define Hn 256
#define En 256
#define DVn 256

#define QT 8          // q rows per CTA in attention kernel
#define KT 32         // k tile (== warp size, lane owns one k)
#define KPAD 260      // padded row stride for kproj smem tile (conflict-free LDS.128)
#define NTILES (Kn / KT)   // 16

// Scratch for projected q/k (no cudaMalloc allowed)
__device__ float g_qp[Bn * Qn * Hn];
__device__ float g_kp[Bn * Kn * Hn];

__device__ __forceinline__ float tanh_fast(float x) {
    float r;
    asm("tanh.approx.f32 %0, %1;" : "=f"(r) : "f"(x));
    return r;
}

// ---------------------------------------------------------------------------
// Kernel 1: projections. rows [0,2048) = queries @ W_q^T, rows [2048,4096) =
// keys @ W_k^T. CTA handles 16 rows x all 256 h, reducing over e in tiles of
// 32 with W staged through smem (coalesced gmem reads, padded smem).
// ---------------------------------------------------------------------------
__global__ __launch_bounds__(256) void proj_kernel(
    const float* __restrict__ queries, const float* __restrict__ keys,
    const float* __restrict__ Wq, const float* __restrict__ Wk)
{
    const int R = 16, ET = 32, WPAD = 36;
    __shared__ float Xs[R][ET];        // 2 KB
    __shared__ float Ws[Hn][WPAD];     // 36.9 KB

    int row0 = blockIdx.x * R;
    bool isK = (row0 >= Bn * Qn);
    const float* src = isK ? keys : queries;
    const float* W   = isK ? Wk : Wq;
    float* dst       = isK ? g_kp : g_qp;
    int lrow0 = isK ? (row0 - Bn * Qn) : row0;

    int tid = threadIdx.x;
    float acc[R];
#pragma unroll
    for (int r = 0; r < R; r++) acc[r] = 0.f;

    for (int et = 0; et < En; et += ET) {
        // Ws: 256 rows x 32 cols = 2048 float4; 8 per thread, coalesced
#pragma unroll
        for (int i = 0; i < 8; i++) {
            int idx = i * 256 + tid;          // float4 index
            int r = idx >> 3, c4 = idx & 7;   // 8 float4 per row
            float4 v = *reinterpret_cast<const float4*>(&W[r * En + et + c4 * 4]);
            *reinterpret_cast<float4*>(&Ws[r][c4 * 4]) = v;
        }
        // Xs: 16 rows x 32 cols = 128 float4
        if (tid < 128) {
            int r = tid >> 3, c4 = tid & 7;
            float4 v = *reinterpret_cast<const float4*>(&src[(lrow0 + r) * En + et + c4 * 4]);
            *reinterpret_cast<float4*>(&Xs[r][c4 * 4]) = v;
        }
        __syncthreads();

        int h = tid;
#pragma unroll
        for (int c4 = 0; c4 < 8; c4++) {
            float4 w = *reinterpret_cast<const float4*>(&Ws[h][c4 * 4]);
#pragma unroll
            for (int r = 0; r < R; r++) {
                float4 x = *reinterpret_cast<const float4*>(&Xs[r][c4 * 4]);
                acc[r] += w.x * x.x;
                acc[r] += w.y * x.y;
                acc[r] += w.z * x.z;
                acc[r] += w.w * x.w;
            }
        }
        __syncthreads();
    }
    int h = tid;
#pragma unroll
    for (int r = 0; r < R; r++)
        dst[(lrow0 + r) * Hn + h] = acc[r];
}

// ---------------------------------------------------------------------------
// Kernel 2: fused score (tanh reduce over h) + softmax + attn@values.
// Grid (Q/QT, B), 256 threads. warp = q-row within tile, lane = k within
// a 32-wide k tile. kproj tile staged in smem with stride-260 padding.
// ---------------------------------------------------------------------------
__global__ __launch_bounds__(256, 2) void attn_kernel(
    const float* __restrict__ values, const float* __restrict__ wv_g,
    float* __restrict__ out)
{
    extern __shared__ float sm[];
    float* qps  = sm;                     // QT*256   = 2048 floats
    float* wvs  = qps + QT * 256;         // 256
    float* es   = wvs + 256;              // QT*Kn    = 4096
    float* invs = es + QT * Kn;           // 8 (padded)
    float* kps  = invs + 8;               // KT*KPAD  = 8320   (16B-aligned offset)

    int b  = blockIdx.y;
    int q0 = blockIdx.x * QT;
    int tid  = threadIdx.x;
    int warp = tid >> 5;
    int lane = tid & 31;
    int qt = warp;

    // load q-proj tile (QT*256 floats = 512 float4)
    const float* qp = &g_qp[(b * Qn + q0) * Hn];
#pragma unroll
    for (int i = 0; i < 2; i++) {
        int idx = i * 256 + tid;
        reinterpret_cast<float4*>(qps)[idx] = reinterpret_cast<const float4*>(qp)[idx];
    }
    if (tid < 64)
        reinterpret_cast<float4*>(wvs)[tid] = reinterpret_cast<const float4*>(wv_g)[tid];

    const float* kp = &g_kp[b * Kn * Hn];
    float m = -CUDART_INF_F;

    for (int t = 0; t < NTILES; t++) {
        __syncthreads();
        // stage kproj tile: KT rows x 256 floats = 2048 float4; 8 per thread
#pragma unroll
        for (int i = 0; i < 8; i++) {
            int idx = i * 256 + tid;
            int r = idx >> 6, c4 = idx & 63;
            float4 v = reinterpret_cast<const float4*>(&kp[(t * KT + r) * Hn])[c4];
            *reinterpret_cast<float4*>(&kps[r * KPAD + c4 * 4]) = v;
        }
        __syncthreads();

        const float* kr = &kps[lane * KPAD];
        const float* qr = &qps[qt * 256];
        float acc = 0.f;
#pragma unroll 16
        for (int h4 = 0; h4 < 64; h4++) {
            float4 kv = *reinterpret_cast<const float4*>(&kr[h4 * 4]);
            float4 qv = *reinterpret_cast<const float4*>(&qr[h4 * 4]);
            float4 wv = *reinterpret_cast<const float4*>(&wvs[h4 * 4]);
            acc += wv.x * tanh_fast(qv.x + kv.x);
            acc += wv.y * tanh_fast(qv.y + kv.y);
            acc += wv.z * tanh_fast(qv.z + kv.z);
            acc += wv.w * tanh_fast(qv.w + kv.w);
        }
        es[qt * Kn + t * KT + lane] = acc;   // raw score for now
        m = fmaxf(m, acc);
    }

    // per-row softmax (warp `qt` owns row qt: it produced all 512 scores)
#pragma unroll
    for (int o = 16; o; o >>= 1) m = fmaxf(m, __shfl_xor_sync(0xffffffffu, m, o));
    float sum = 0.f;
    for (int t = 0; t < NTILES; t++) {
        float sc = es[qt * Kn + t * KT + lane];
        float e = __expf(sc - m);
        es[qt * Kn + t * KT + lane] = e;
        sum += e;
    }
#pragma unroll
    for (int o = 16; o; o >>= 1) sum += __shfl_xor_sync(0xffffffffu, sum, o);
    if (lane == 0) invs[qt] = 1.f / sum;
    __syncthreads();

    // AV: thread owns d = tid; coalesced values loads, broadcast e from smem
    int d = tid;
    float acc[QT];
#pragma unroll
    for (int j = 0; j < QT; j++) acc[j] = 0.f;
    const float* vb = &values[b * Kn * DVn + d];

    for (int k = 0; k < Kn; k += 4) {
        float v0 = __ldg(&vb[(k + 0) * DVn]);
        float v1 = __ldg(&vb[(k + 1) * DVn]);
        float v2 = __ldg(&vb[(k + 2) * DVn]);
        float v3 = __ldg(&vb[(k + 3) * DVn]);
#pragma unroll
        for (int j = 0; j < QT; j++) {
            float4 e = *reinterpret_cast<const float4*>(&es[j * Kn + k]);
            acc[j] += e.x * v0;
            acc[j] += e.y * v1;
            acc[j] += e.z * v2;
            acc[j] += e.w * v3;
        }
    }
#pragma unroll
    for (int j = 0; j < QT; j++)
        out[(b * Qn + q0 + j) * DVn + d] = acc[j] * invs[j];
}

// ---------------------------------------------------------------------------
extern "C" void kernel_launch(void* const* d_in, const int* in_sizes, int n_in,
                              void* d_out, int out_size)
{
    const float* queries = (const float*)d_in[0];
    const float* keys    = (const float*)d_in[1];
    const float* values  = (const float*)d_in[2];
    const float* Wq      = (const float*)d_in[3];
    const float* Wk      = (const float*)d_in[4];
    const float* wv      = (const float*)d_in[5];
    float* out = (float*)d_out;

    // projections: (2048 q-rows + 2048 k-rows) / 16 rows per CTA = 256 CTAs
    proj_kernel<<<256, 256>>>(queries, keys, Wq, Wk);

    const int smem2 = (QT * 256 + 256 + QT * Kn + 8 + KT * KPAD) * (int)sizeof(float); // 58912 B
    cudaFuncSetAttribute(attn_kernel, cudaFuncAttributeMaxDynamicSharedMemorySize, smem2);
    attn_kernel<<<dim3(Qn / QT, Bn), 256, smem2>>>(values, wv, out);
}

// round 2
// speedup vs baseline: 1.0687x; 1.0687x over previous
#include <cuda_runtime.h>
#include <math_constants.h>

#define Bn 4
#define Qn 512
#define Kn 512
#define Hn 256
#define En 256
#define DVn 256

#define QT 8          // q rows per CTA
#define NTILES 2      // two 256-wide k blocks (8 warps x 32 lanes each)

// Scratch for projected q/k (no cudaMalloc allowed)
__device__ float g_qp[Bn * Qn * Hn];
__device__ float g_kp[Bn * Kn * Hn];

__device__ __forceinline__ float tanh_fast(float x) {
    float r;
    asm("tanh.approx.f32 %0, %1;" : "=f"(r) : "f"(x));
    return r;
}

// ---------------------------------------------------------------------------
// Kernel 1: projections. rows [0,2048) = queries @ W_q^T, rows [2048,4096) =
// keys @ W_k^T. CTA handles 16 rows x all 256 h, reducing over e in tiles of
// 32 with W staged through smem (coalesced gmem reads, padded smem).
// ---------------------------------------------------------------------------
__global__ __launch_bounds__(256) void proj_kernel(
    const float* __restrict__ queries, const float* __restrict__ keys,
    const float* __restrict__ Wq, const float* __restrict__ Wk)
{
    const int R = 16, ET = 32, WPAD = 36;
    __shared__ float Xs[R][ET];        // 2 KB
    __shared__ float Ws[Hn][WPAD];     // 36.9 KB

    int row0 = blockIdx.x * R;
    bool isK = (row0 >= Bn * Qn);
    const float* src = isK ? keys : queries;
    const float* W   = isK ? Wk : Wq;
    float* dst       = isK ? g_kp : g_qp;
    int lrow0 = isK ? (row0 - Bn * Qn) : row0;

    int tid = threadIdx.x;
    float acc[R];
#pragma unroll
    for (int r = 0; r < R; r++) acc[r] = 0.f;

    for (int et = 0; et < En; et += ET) {
#pragma unroll
        for (int i = 0; i < 8; i++) {
            int idx = i * 256 + tid;          // float4 index
            int r = idx >> 3, c4 = idx & 7;   // 8 float4 per row
            float4 v = *reinterpret_cast<const float4*>(&W[r * En + et + c4 * 4]);
            *reinterpret_cast<float4*>(&Ws[r][c4 * 4]) = v;
        }
        if (tid < 128) {
            int r = tid >> 3, c4 = tid & 7;
            float4 v = *reinterpret_cast<const float4*>(&src[(lrow0 + r) * En + et + c4 * 4]);
            *reinterpret_cast<float4*>(&Xs[r][c4 * 4]) = v;
        }
        __syncthreads();

        int h = tid;
#pragma unroll
        for (int c4 = 0; c4 < 8; c4++) {
            float4 w = *reinterpret_cast<const float4*>(&Ws[h][c4 * 4]);
#pragma unroll
            for (int r = 0; r < R; r++) {
                float4 x = *reinterpret_cast<const float4*>(&Xs[r][c4 * 4]);
                acc[r] += w.x * x.x;
                acc[r] += w.y * x.y;
                acc[r] += w.z * x.z;
                acc[r] += w.w * x.w;
            }
        }
        __syncthreads();
    }
    int h = tid;
#pragma unroll
    for (int r = 0; r < R; r++)
        dst[(lrow0 + r) * Hn + h] = acc[r];
}

// ---------------------------------------------------------------------------
// Kernel 2: fused score + softmax + attn@values.
// Grid (Q/QT, B), 256 threads. Register-tiled score loop:
//   warp w, k-block kb: lane owns k = kb*256 + w*32 + lane.
//   kv (8 floats of lane's k-row) and wv chunk live in REGISTERS (kv straight
//   from L2-resident g_kp); qv is a warp-uniform smem broadcast (conflict-free,
//   amortized over 32 lanes). acc[QT] accumulates the full score over h.
// No smem staging, no syncs in the hot loop -> MUFU-bound.
// ---------------------------------------------------------------------------
__global__ __launch_bounds__(256, 2) void attn_kernel(
    const float* __restrict__ values, const float* __restrict__ wv_g,
    float* __restrict__ out)
{
    __shared__ float qps[QT * Hn];     // 2048
    __shared__ float wvs[Hn];          // 256
    __shared__ float es[QT * Kn];      // 4096
    __shared__ float invs[QT];

    int b  = blockIdx.y;
    int q0 = blockIdx.x * QT;
    int tid  = threadIdx.x;
    int warp = tid >> 5;
    int lane = tid & 31;

    // load q-proj tile (QT*256 floats = 512 float4, 2 per thread)
    const float* qp = &g_qp[(b * Qn + q0) * Hn];
#pragma unroll
    for (int i = 0; i < 2; i++) {
        int idx = i * 256 + tid;
        reinterpret_cast<float4*>(qps)[idx] = reinterpret_cast<const float4*>(qp)[idx];
    }
    if (tid < 64)
        reinterpret_cast<float4*>(wvs)[tid] = reinterpret_cast<const float4*>(wv_g)[tid];
    __syncthreads();

    const float* kpb = &g_kp[b * Kn * Hn];

#pragma unroll 1
    for (int kb = 0; kb < NTILES; kb++) {
        int k = kb * 256 + warp * 32 + lane;
        const float* kr = &kpb[k * Hn];

        float acc[QT];
#pragma unroll
        for (int q = 0; q < QT; q++) acc[q] = 0.f;

#pragma unroll 2
        for (int hc = 0; hc < Hn / 8; hc++) {
            float4 kv0 = __ldg(reinterpret_cast<const float4*>(&kr[hc * 8]));
            float4 kv1 = __ldg(reinterpret_cast<const float4*>(&kr[hc * 8 + 4]));
            float4 wv0 = *reinterpret_cast<const float4*>(&wvs[hc * 8]);
            float4 wv1 = *reinterpret_cast<const float4*>(&wvs[hc * 8 + 4]);
#pragma unroll
            for (int q = 0; q < QT; q++) {
                float4 qv0 = *reinterpret_cast<const float4*>(&qps[q * Hn + hc * 8]);
                float4 qv1 = *reinterpret_cast<const float4*>(&qps[q * Hn + hc * 8 + 4]);
                float a = acc[q];
                a += wv0.x * tanh_fast(qv0.x + kv0.x);
                a += wv0.y * tanh_fast(qv0.y + kv0.y);
                a += wv0.z * tanh_fast(qv0.z + kv0.z);
                a += wv0.w * tanh_fast(qv0.w + kv0.w);
                a += wv1.x * tanh_fast(qv1.x + kv1.x);
                a += wv1.y * tanh_fast(qv1.y + kv1.y);
                a += wv1.z * tanh_fast(qv1.z + kv1.z);
                a += wv1.w * tanh_fast(qv1.w + kv1.w);
                acc[q] = a;
            }
        }
#pragma unroll
        for (int q = 0; q < QT; q++)
            es[q * Kn + k] = acc[q];
    }
    __syncthreads();

    // softmax: warp w owns row w (16 scores per lane)
    {
        int row = warp;
        float sc[Kn / 32];
        float m = -CUDART_INF_F;
#pragma unroll
        for (int i = 0; i < Kn / 32; i++) {
            sc[i] = es[row * Kn + i * 32 + lane];
            m = fmaxf(m, sc[i]);
        }
#pragma unroll
        for (int o = 16; o; o >>= 1) m = fmaxf(m, __shfl_xor_sync(0xffffffffu, m, o));
        float sum = 0.f;
#pragma unroll
        for (int i = 0; i < Kn / 32; i++) {
            float e = __expf(sc[i] - m);
            es[row * Kn + i * 32 + lane] = e;
            sum += e;
        }
#pragma unroll
        for (int o = 16; o; o >>= 1) sum += __shfl_xor_sync(0xffffffffu, sum, o);
        if (lane == 0) invs[row] = 1.f / sum;
    }
    __syncthreads();

    // AV: thread owns output dim d = tid; coalesced values loads
    int d = tid;
    float acc[QT];
#pragma unroll
    for (int j = 0; j < QT; j++) acc[j] = 0.f;
    const float* vb = &values[b * Kn * DVn + d];

    for (int k = 0; k < Kn; k += 4) {
        float v0 = __ldg(&vb[(k + 0) * DVn]);
        float v1 = __ldg(&vb[(k + 1) * DVn]);
        float v2 = __ldg(&vb[(k + 2) * DVn]);
        float v3 = __ldg(&vb[(k + 3) * DVn]);
#pragma unroll
        for (int j = 0; j < QT; j++) {
            float4 e = *reinterpret_cast<const float4*>(&es[j * Kn + k]);
            acc[j] += e.x * v0;
            acc[j] += e.y * v1;
            acc[j] += e.z * v2;
            acc[j] += e.w * v3;
        }
    }
#pragma unroll
    for (int j = 0; j < QT; j++)
        out[(b * Qn + q0 + j) * DVn + d] = acc[j] * invs[j];
}

// ---------------------------------------------------------------------------
extern "C" void kernel_launch(void* const* d_in, const int* in_sizes, int n_in,
                              void* d_out, int out_size)
{
    const float* queries = (const float*)d_in[0];
    const float* keys    = (const float*)d_in[1];
    const float* values  = (const float*)d_in[2];
    const float* Wq      = (const float*)d_in[3];
    const float* Wk      = (const float*)d_in[4];
    const float* wv      = (const float*)d_in[5];
    float* out = (float*)d_out;

    proj_kernel<<<256, 256>>>(queries, keys, Wq, Wk);
    attn_kernel<<<dim3(Qn / QT, Bn), 256>>>(values, wv, out);
}

// round 3
// speedup vs baseline: 1.2219x; 1.1433x over previous
#include <cuda_runtime.h>
#include <math_constants.h>

#define Bn 4
#define Qn 512
#define Kn 512
#define Hn 256
#define En 256
#define DVn 256

#define QT 8          // q rows per CTA

// Scratch for projected q/k (no cudaMalloc allowed)
__device__ float g_qp[Bn * Qn * Hn];
__device__ float g_kp[Bn * Kn * Hn];

__device__ __forceinline__ float tanh_fast(float x) {
    float r;
    asm("tanh.approx.f32 %0, %1;" : "=f"(r) : "f"(x));
    return r;
}

// ---------------------------------------------------------------------------
// Kernel 1: projections. rows [0,2048) = queries @ W_q^T, rows [2048,4096) =
// keys @ W_k^T.
// ---------------------------------------------------------------------------
__global__ __launch_bounds__(256) void proj_kernel(
    const float* __restrict__ queries, const float* __restrict__ keys,
    const float* __restrict__ Wq, const float* __restrict__ Wk)
{
    const int R = 16, ET = 32, WPAD = 36;
    __shared__ float Xs[R][ET];
    __shared__ float Ws[Hn][WPAD];

    int row0 = blockIdx.x * R;
    bool isK = (row0 >= Bn * Qn);
    const float* src = isK ? keys : queries;
    const float* W   = isK ? Wk : Wq;
    float* dst       = isK ? g_kp : g_qp;
    int lrow0 = isK ? (row0 - Bn * Qn) : row0;

    int tid = threadIdx.x;
    float acc[R];
#pragma unroll
    for (int r = 0; r < R; r++) acc[r] = 0.f;

    for (int et = 0; et < En; et += ET) {
#pragma unroll
        for (int i = 0; i < 8; i++) {
            int idx = i * 256 + tid;
            int r = idx >> 3, c4 = idx & 7;
            float4 v = *reinterpret_cast<const float4*>(&W[r * En + et + c4 * 4]);
            *reinterpret_cast<float4*>(&Ws[r][c4 * 4]) = v;
        }
        if (tid < 128) {
            int r = tid >> 3, c4 = tid & 7;
            float4 v = *reinterpret_cast<const float4*>(&src[(lrow0 + r) * En + et + c4 * 4]);
            *reinterpret_cast<float4*>(&Xs[r][c4 * 4]) = v;
        }
        __syncthreads();

        int h = tid;
#pragma unroll
        for (int c4 = 0; c4 < 8; c4++) {
            float4 w = *reinterpret_cast<const float4*>(&Ws[h][c4 * 4]);
#pragma unroll
            for (int r = 0; r < R; r++) {
                float4 x = *reinterpret_cast<const float4*>(&Xs[r][c4 * 4]);
                acc[r] += w.x * x.x;
                acc[r] += w.y * x.y;
                acc[r] += w.z * x.z;
                acc[r] += w.w * x.w;
            }
        }
        __syncthreads();
    }
    int h = tid;
#pragma unroll
    for (int r = 0; r < R; r++)
        dst[(lrow0 + r) * Hn + h] = acc[r];
}

// ---------------------------------------------------------------------------
// Kernel 2: fused score + softmax + attn@values.
// 512 threads (16 warps): warp w owns k = w*32 + lane, single k pass.
// kv prefetched one h-chunk ahead (hides L2 latency under MUFU work).
// qv/wv are warp-uniform smem broadcasts. 8 warps/SMSP at occ 2.
// ---------------------------------------------------------------------------
__global__ __launch_bounds__(512, 2) void attn_kernel(
    const float* __restrict__ values, const float* __restrict__ wv_g,
    float* __restrict__ out)
{
    __shared__ float qps[QT * Hn];        // 2048
    __shared__ float wvs[Hn];             // 256
    __shared__ float es[QT * Kn];         // 4096
    __shared__ float invs[QT];
    __shared__ float avred[QT * DVn];     // 2048 (AV partial combine)

    int b  = blockIdx.y;
    int q0 = blockIdx.x * QT;
    int tid  = threadIdx.x;
    int warp = tid >> 5;
    int lane = tid & 31;

    // load q-proj tile (512 float4, 1 per thread) + wv
    const float* qp = &g_qp[(b * Qn + q0) * Hn];
    reinterpret_cast<float4*>(qps)[tid] = reinterpret_cast<const float4*>(qp)[tid];
    if (tid < 64)
        reinterpret_cast<float4*>(wvs)[tid] = reinterpret_cast<const float4*>(wv_g)[tid];
    __syncthreads();

    // ---- score stage: lane owns k-row, full h reduction in registers ----
    {
        int k = warp * 32 + lane;                   // 0..511
        const float* kr = &g_kp[(b * Kn + k) * Hn];

        float acc[QT];
#pragma unroll
        for (int q = 0; q < QT; q++) acc[q] = 0.f;

        float4 kv0 = __ldg(reinterpret_cast<const float4*>(kr));
        float4 kv1 = __ldg(reinterpret_cast<const float4*>(kr + 4));

#pragma unroll 2
        for (int hc = 0; hc < Hn / 8; hc++) {
            float4 nv0, nv1;
            if (hc + 1 < Hn / 8) {
                nv0 = __ldg(reinterpret_cast<const float4*>(&kr[(hc + 1) * 8]));
                nv1 = __ldg(reinterpret_cast<const float4*>(&kr[(hc + 1) * 8 + 4]));
            }
            float4 wv0 = *reinterpret_cast<const float4*>(&wvs[hc * 8]);
            float4 wv1 = *reinterpret_cast<const float4*>(&wvs[hc * 8 + 4]);
#pragma unroll
            for (int q = 0; q < QT; q++) {
                float4 qv0 = *reinterpret_cast<const float4*>(&qps[q * Hn + hc * 8]);
                float4 qv1 = *reinterpret_cast<const float4*>(&qps[q * Hn + hc * 8 + 4]);
                float a = acc[q];
                a += wv0.x * tanh_fast(qv0.x + kv0.x);
                a += wv0.y * tanh_fast(qv0.y + kv0.y);
                a += wv0.z * tanh_fast(qv0.z + kv0.z);
                a += wv0.w * tanh_fast(qv0.w + kv0.w);
                a += wv1.x * tanh_fast(qv1.x + kv1.x);
                a += wv1.y * tanh_fast(qv1.y + kv1.y);
                a += wv1.z * tanh_fast(qv1.z + kv1.z);
                a += wv1.w * tanh_fast(qv1.w + kv1.w);
                acc[q] = a;
            }
            kv0 = nv0; kv1 = nv1;
        }
#pragma unroll
        for (int q = 0; q < QT; q++)
            es[q * Kn + k] = acc[q];
    }
    __syncthreads();

    // ---- softmax: warps 0..7, warp w owns row w ----
    if (warp < QT) {
        int row = warp;
        float sc[Kn / 32];
        float m = -CUDART_INF_F;
#pragma unroll
        for (int i = 0; i < Kn / 32; i++) {
            sc[i] = es[row * Kn + i * 32 + lane];
            m = fmaxf(m, sc[i]);
        }
#pragma unroll
        for (int o = 16; o; o >>= 1) m = fmaxf(m, __shfl_xor_sync(0xffffffffu, m, o));
        float sum = 0.f;
#pragma unroll
        for (int i = 0; i < Kn / 32; i++) {
            float e = __expf(sc[i] - m);
            es[row * Kn + i * 32 + lane] = e;
            sum += e;
        }
#pragma unroll
        for (int o = 16; o; o >>= 1) sum += __shfl_xor_sync(0xffffffffu, sum, o);
        if (lane == 0) invs[row] = 1.f / sum;
    }
    __syncthreads();

    // ---- AV: split k range across the two thread halves ----
    int d    = tid & (DVn - 1);
    int half = tid >> 8;                 // 0 or 1
    int k0   = half * (Kn / 2);

    float acc[QT];
#pragma unroll
    for (int j = 0; j < QT; j++) acc[j] = 0.f;
    const float* vb = &values[b * Kn * DVn + d];

    for (int k = k0; k < k0 + Kn / 2; k += 4) {
        float v0 = __ldg(&vb[(k + 0) * DVn]);
        float v1 = __ldg(&vb[(k + 1) * DVn]);
        float v2 = __ldg(&vb[(k + 2) * DVn]);
        float v3 = __ldg(&vb[(k + 3) * DVn]);
#pragma unroll
        for (int j = 0; j < QT; j++) {
            float4 e = *reinterpret_cast<const float4*>(&es[j * Kn + k]);
            acc[j] += e.x * v0;
            acc[j] += e.y * v1;
            acc[j] += e.z * v2;
            acc[j] += e.w * v3;
        }
    }
    if (half == 1) {
#pragma unroll
        for (int j = 0; j < QT; j++)
            avred[j * DVn + d] = acc[j];
    }
    __syncthreads();
    if (half == 0) {
#pragma unroll
        for (int j = 0; j < QT; j++)
            out[(b * Qn + q0 + j) * DVn + d] = (acc[j] + avred[j * DVn + d]) * invs[j];
    }
}

// ---------------------------------------------------------------------------
extern "C" void kernel_launch(void* const* d_in, const int* in_sizes, int n_in,
                              void* d_out, int out_size)
{
    const float* queries = (const float*)d_in[0];
    const float* keys    = (const float*)d_in[1];
    const float* values  = (const float*)d_in[2];
    const float* Wq      = (const float*)d_in[3];
    const float* Wk      = (const float*)d_in[4];
    const float* wv      = (const float*)d_in[5];
    float* out = (float*)d_out;

    proj_kernel<<<256, 256>>>(queries, keys, Wq, Wk);
    attn_kernel<<<dim3(Qn / QT, Bn), 512>>>(values, wv, out);
}